// round 10
// baseline (speedup 1.0000x reference)
#include <cuda_runtime.h>
#include <cstdint>

// Problem dims
#define BSZ   4096
#define LSEQ  64
#define EDIM  32
#define HDIM  32
#define GDIM  256
#define F2DIM 512
#define ADIM  1000
#define NSF   32768   // 8 * BSZ
#define NS    36864   // 9 * BSZ
#define VSIZE 50000
#define VPAD  50048   // 391 * 128

typedef unsigned long long ull;

// ---------------- scratch (device globals: allocation-free) ----------------
__device__ float d_hq[BSZ * HDIM];                       // [4096, 32]
__device__ float d_X0[(size_t)NSF * 64];                 // [32768, 64]
__device__ float d_X1[(size_t)NSF * GDIM];               // [32768, 256]
__device__ float d_X2[(size_t)NSF * GDIM];               // [32768, 256]
__device__ float d_gsum[(size_t)BSZ * GDIM];             // [4096, 256]
__device__ float d_Y1[(size_t)BSZ * GDIM];               // [4096, 256]
__device__ float d_Y2[(size_t)BSZ * F2DIM];              // [4096, 512]
__device__ float d_brel[8 * GDIM];                       // per-relation g1 bias
__device__ float d_g1w[GDIM * 64];                       // g1W cols 0..63, dense

// Repacked LSTM weights
__device__ float d_wpkq[128 * 32];   // [j4g][e]  from qWih
__device__ float d_wpks[128 * 32];
__device__ float d_bpkq[128];
__device__ float d_bpks[128];
__device__ float d_whhq[32 * 128];   // [j][g*32 + k]  from qWhh
__device__ float d_whhs[32 * 128];

// Precomputed input projections: xproj[v][j*4+g] = Wih·emb[v] + b
__device__ float d_xpq[(size_t)VPAD * 128];
__device__ float d_xps[(size_t)VPAD * 128];

struct SfPtrs { const int* p[8]; };

__device__ __forceinline__ float ftanh_(float x) {
    float r;
    asm("tanh.approx.f32 %0, %1;" : "=f"(r) : "f"(x));
    return r;
}
__device__ __forceinline__ float fsig(float x) {
    return fmaf(ftanh_(0.5f * x), 0.5f, 0.5f);
}
__device__ __forceinline__ ull pack2(float a, float b) {
    ull r; asm("mov.b64 %0, {%1, %2};" : "=l"(r) : "f"(a), "f"(b)); return r;
}
__device__ __forceinline__ float2 unpack2(ull v) {
    float2 r; asm("mov.b64 {%0, %1}, %2;" : "=f"(r.x), "=f"(r.y) : "l"(v)); return r;
}
#define FMA2(acc, a, b) asm("fma.rn.f32x2 %0, %1, %2, %0;" : "+l"(acc) : "l"(a), "l"(b))

__device__ __forceinline__ uint32_t f2tf32(float x) {
    uint32_t r; asm("cvt.rna.tf32.f32 %0, %1;" : "=r"(r) : "f"(x)); return r;
}
__device__ __forceinline__ void tf32_split(float x, uint32_t& hi, uint32_t& lo) {
    hi = f2tf32(x);
    lo = f2tf32(x - __uint_as_float(hi));
}
__device__ __forceinline__ void mma_tf32(float* d, const uint32_t* a, const uint32_t* b) {
    asm volatile(
        "mma.sync.aligned.m16n8k8.row.col.f32.tf32.tf32.f32 "
        "{%0,%1,%2,%3}, {%4,%5,%6,%7}, {%8,%9}, {%0,%1,%2,%3};"
        : "+f"(d[0]), "+f"(d[1]), "+f"(d[2]), "+f"(d[3])
        : "r"(a[0]), "r"(a[1]), "r"(a[2]), "r"(a[3]), "r"(b[0]), "r"(b[1]));
}

// ---------------------------------------------------------------------------
// Repack LSTM weights.
// ---------------------------------------------------------------------------
__global__ void pack_kernel(
    const float* __restrict__ qWih, const float* __restrict__ qWhh, const float* __restrict__ qb,
    const float* __restrict__ sWih, const float* __restrict__ sWhh, const float* __restrict__ sb)
{
    int idx = blockIdx.x * blockDim.x + threadIdx.x;   // 0..4095
    if (idx < 4096) {
        {   // Wih pack: idx = j4g*32 + e
            int j4g = idx >> 5, e = idx & 31;
            int j = j4g >> 2, g = j4g & 3;
            int src = (g * 32 + j) * 32 + e;
            d_wpkq[idx] = qWih[src];
            d_wpks[idx] = sWih[src];
        }
        {   // Whh pack: idx = j*128 + g*32 + k
            int j = idx >> 7, g = (idx >> 5) & 3, k = idx & 31;
            int src = (g * 32 + j) * 32 + k;
            d_whhq[idx] = qWhh[src];
            d_whhs[idx] = sWhh[src];
        }
    }
    if (idx < 128) {
        int j = idx >> 2, g = idx & 3;
        d_bpkq[idx] = qb[g * 32 + j];
        d_bpks[idx] = sb[g * 32 + j];
    }
}

// Per-relation g1 bias + dense g1W repack.
__global__ void bias_rel_kernel(const float* __restrict__ g1W, const float* __restrict__ g1b)
{
    int idx = blockIdx.x * blockDim.x + threadIdx.x;
    if (idx < 8 * GDIM) {
        int r = idx >> 8, n = idx & 255;
        d_brel[idx] = g1b[n] + (float)r * g1W[n * 65 + 64];
    }
    if (idx < GDIM * 64) {
        int n = idx >> 6, k = idx & 63;
        d_g1w[idx] = g1W[n * 65 + k];
    }
}

// ---------------------------------------------------------------------------
// LSTM recurrence: warp-paired 2 threads/sample. Lanes (2u,2u+1) share sample u;
// even lane owns j 0..15, odd lane j 16..31. h exchanged via 64-bit shfl_xor
// (no barriers, no smem state). c and h fully register-resident.
// 128 threads/block = 64 samples -> 576 blocks (~4/SM, 16 warps/SM).
// ---------------------------------------------------------------------------
__global__ __launch_bounds__(128) void lstm_kernel(const int* __restrict__ q, SfPtrs sf)
{
    __shared__ __align__(16) float sWhh[4096];   // packed Whh [j][g*32+k]

    const int tid  = threadIdx.x;
    const int lane = tid & 31;
    const int half = lane & 1;        // 0: j 0..15, 1: j 16..31
    const bool isQ = (blockIdx.x < (BSZ / 64));
    const float* wsrc = isQ ? d_whhq : d_whhs;
    const float* xp   = isQ ? d_xpq  : d_xps;

    for (int i = tid; i < 4096; i += 128) sWhh[i] = wsrc[i];
    __syncthreads();

    // sample for this pair
    const int s = blockIdx.x * 64 + (tid >> 1);
    const int* tok;
    int b, ss = 0;
    if (isQ) {
        b = s;
        tok = q + (size_t)b * LSEQ;
    } else {
        ss = s - BSZ;
        int r = ss >> 12;
        b = ss & (BSZ - 1);
        tok = sf.p[r] + (size_t)b * LSEQ;
    }

    const int jbase = half * 16;

    ull hown[8];                      // own 16 h values packed
    float c[16];
#pragma unroll
    for (int p = 0; p < 8; p++) hown[p] = 0ull;
#pragma unroll
    for (int jj = 0; jj < 16; jj++) c[jj] = 0.f;

    for (int t = 0; t < LSEQ; t++) {
        const int token = tok[t];
        const float4* xrow = reinterpret_cast<const float4*>(xp + (size_t)token * 128);

        // full h vector: own half + partner half via shfl_xor(1)
        ull h2[16];
#pragma unroll
        for (int p = 0; p < 8; p++) {
            h2[jbase / 2 + p] = hown[p];
            h2[(jbase ^ 16) / 2 + p] = __shfl_xor_sync(0xffffffffu, hown[p], 1);
        }

        ull hnew[8];
#pragma unroll 4
        for (int jj = 0; jj < 16; jj++) {
            const int j = jbase + jj;
            const float4 xg = __ldg(&xrow[j]);
            const ulonglong2* Wj = reinterpret_cast<const ulonglong2*>(sWhh + j * 128);
            ull ai = 0, af = 0, ag = 0, ao = 0;   // bit pattern == {0.f,0.f}
#pragma unroll
            for (int p = 0; p < 8; p++) {
                ulonglong2 w;
                w = Wj[p];      FMA2(ai, w.x, h2[2*p]); FMA2(ai, w.y, h2[2*p+1]);
                w = Wj[8 + p];  FMA2(af, w.x, h2[2*p]); FMA2(af, w.y, h2[2*p+1]);
                w = Wj[16 + p]; FMA2(ag, w.x, h2[2*p]); FMA2(ag, w.y, h2[2*p+1]);
                w = Wj[24 + p]; FMA2(ao, w.x, h2[2*p]); FMA2(ao, w.y, h2[2*p+1]);
            }
            float2 vi = unpack2(ai), vf = unpack2(af), vg = unpack2(ag), vo = unpack2(ao);
            const float si  = vi.x + vi.y + xg.x;
            const float sfv = vf.x + vf.y + xg.y;
            const float sg  = vg.x + vg.y + xg.z;
            const float so  = vo.x + vo.y + xg.w;
            float cc = c[jj];
            cc = fsig(sfv) * cc + fsig(si) * ftanh_(sg);
            c[jj] = cc;
            const float hv = fsig(so) * ftanh_(cc);
            if (jj & 1) {
                float2 prev = unpack2(hnew[jj >> 1]);
                hnew[jj >> 1] = pack2(prev.x, hv);
            } else {
                hnew[jj >> 1] = pack2(hv, 0.f);
            }
        }
#pragma unroll
        for (int p = 0; p < 8; p++) hown[p] = hnew[p];
    }

    // final h write: even lane writes floats 0..15, odd lane 16..31
    float* dstf = isQ ? (d_hq + (size_t)b * HDIM) : (d_X0 + (size_t)ss * 64);
    float4* dst = reinterpret_cast<float4*>(dstf) + half * 4;
#pragma unroll
    for (int i = 0; i < 4; i++) {
        float2 a = unpack2(hown[2 * i]);
        float2 bb = unpack2(hown[2 * i + 1]);
        dst[i] = make_float4(a.x, a.y, bb.x, bb.y);
    }
}

// X0[s, 32:64] = hq[b]
__global__ void build_x0_kernel()
{
    int s = blockIdx.x * blockDim.x + threadIdx.x;
    if (s >= NSF) return;
    int b = s & (BSZ - 1);
    const float4* src = reinterpret_cast<const float4*>(d_hq + (size_t)b * HDIM);
    float4* dst = reinterpret_cast<float4*>(d_X0 + (size_t)s * 64 + 32);
#pragma unroll
    for (int i = 0; i < 8; i++) dst[i] = src[i];
}

// ---------------------------------------------------------------------------
// fp32 GEMM (double-buffered) — used only for the xproj precompute (K=32).
// ---------------------------------------------------------------------------
__global__ __launch_bounds__(256, 2) void gemm_kernel(
    const float* __restrict__ A, const float* __restrict__ W,
    const float* __restrict__ bias, float* __restrict__ C,
    int Mr, int N, int K, int lda, int ldw, int doRelu, int biasPerRel)
{
    __shared__ __align__(16) float sA[2][16][132];
    __shared__ __align__(16) float sW[2][16][68];

    const int bm = blockIdx.y * 128;
    const int bn = blockIdx.x * 64;
    const int tid = threadIdx.x;
    const int tx = tid & 15;
    const int ty = tid >> 4;

    float acc[8][4];
#pragma unroll
    for (int i = 0; i < 8; i++)
#pragma unroll
        for (int j = 0; j < 4; j++) acc[i][j] = 0.f;

    const int nk = (K + 15) >> 4;

#pragma unroll
    for (int i = 0; i < 8; i++) {
        int e = tid + i * 256; int m = e >> 4; int kk = e & 15;
        sA[0][kk][m] = (kk < K && (bm + m) < Mr) ? A[(size_t)(bm + m) * lda + kk] : 0.f;
    }
#pragma unroll
    for (int i = 0; i < 4; i++) {
        int e = tid + i * 256; int n = e >> 4; int kk = e & 15;
        sW[0][kk][n] = (kk < K && (bn + n) < N) ? W[(size_t)(bn + n) * ldw + kk] : 0.f;
    }
    __syncthreads();

    for (int kt = 0; kt < nk; kt++) {
        const int cur = kt & 1;
        float pa[8], pw[4];
        const bool has = (kt + 1 < nk);
        if (has) {
            int k0 = (kt + 1) << 4;
#pragma unroll
            for (int i = 0; i < 8; i++) {
                int e = tid + i * 256; int m = e >> 4; int kk = e & 15; int gk = k0 + kk;
                pa[i] = (gk < K && (bm + m) < Mr) ? A[(size_t)(bm + m) * lda + gk] : 0.f;
            }
#pragma unroll
            for (int i = 0; i < 4; i++) {
                int e = tid + i * 256; int n = e >> 4; int kk = e & 15; int gk = k0 + kk;
                pw[i] = (gk < K && (bn + n) < N) ? W[(size_t)(bn + n) * ldw + gk] : 0.f;
            }
        }
#pragma unroll
        for (int kk = 0; kk < 16; kk++) {
            float a[8], w[4];
            float4 a0 = *reinterpret_cast<const float4*>(&sA[cur][kk][ty * 8]);
            float4 a1 = *reinterpret_cast<const float4*>(&sA[cur][kk][ty * 8 + 4]);
            float4 w0 = *reinterpret_cast<const float4*>(&sW[cur][kk][tx * 4]);
            a[0]=a0.x; a[1]=a0.y; a[2]=a0.z; a[3]=a0.w;
            a[4]=a1.x; a[5]=a1.y; a[6]=a1.z; a[7]=a1.w;
            w[0]=w0.x; w[1]=w0.y; w[2]=w0.z; w[3]=w0.w;
#pragma unroll
            for (int i = 0; i < 8; i++)
#pragma unroll
                for (int j = 0; j < 4; j++) acc[i][j] += a[i] * w[j];
        }
        if (has) {
            const int nxt = cur ^ 1;
#pragma unroll
            for (int i = 0; i < 8; i++) {
                int e = tid + i * 256; int m = e >> 4; int kk = e & 15;
                sA[nxt][kk][m] = pa[i];
            }
#pragma unroll
            for (int i = 0; i < 4; i++) {
                int e = tid + i * 256; int n = e >> 4; int kk = e & 15;
                sW[nxt][kk][n] = pw[i];
            }
            __syncthreads();
        }
    }

    const float* brow = biasPerRel ? (bias + (size_t)(bm >> 12) * N) : bias;
#pragma unroll
    for (int i = 0; i < 8; i++) {
        int m = bm + ty * 8 + i;
#pragma unroll
        for (int j = 0; j < 4; j++) {
            int n = bn + tx * 4 + j;
            if (n < N) {
                float v = acc[i][j] + brow[n];
                if (doRelu) v = fmaxf(v, 0.f);
                C[(size_t)m * N + n] = v;
            }
        }
    }
}

// ---------------------------------------------------------------------------
// 3xTF32 tensor-core GEMM (single-buffered, static smem — R8 known-good).
// C[M,N] = act(A[M,K(lda)] @ W[N,K(ldw)]^T + bias)
// Requirements: M % 128 == 0, K % 32 == 0, lda % 4 == 0, ldw % 4 == 0.
// ---------------------------------------------------------------------------
__global__ __launch_bounds__(256) void gemm_tc_kernel(
    const float* __restrict__ A, const float* __restrict__ W,
    const float* __restrict__ bias, float* __restrict__ C,
    int N, int K, int lda, int ldw, int doRelu, int biasPerRel)
{
    __shared__ __align__(16) float sA[128][36];
    __shared__ __align__(16) float sW[64][36];

    const int bm = blockIdx.y * 128;
    const int bn = blockIdx.x * 64;
    const int tid  = threadIdx.x;
    const int lane = tid & 31;
    const int wid  = tid >> 5;
    const int warpM = wid & 3;
    const int warpN = wid >> 2;
    const int wm = warpM * 32;
    const int wn = warpN * 32;
    const int lr = lane >> 2;
    const int lc = lane & 3;

    float acc[2][4][4];
#pragma unroll
    for (int mt = 0; mt < 2; mt++)
#pragma unroll
        for (int nt = 0; nt < 4; nt++)
#pragma unroll
            for (int r = 0; r < 4; r++) acc[mt][nt][r] = 0.f;

    for (int k0 = 0; k0 < K; k0 += 32) {
#pragma unroll
        for (int i = 0; i < 4; i++) {
            int e = tid + i * 256;
            int m = e >> 3;
            int kq = e & 7;
            float4 v = *reinterpret_cast<const float4*>(&A[(size_t)(bm + m) * lda + k0 + kq * 4]);
            *reinterpret_cast<float4*>(&sA[m][kq * 4]) = v;
        }
#pragma unroll
        for (int i = 0; i < 2; i++) {
            int e = tid + i * 256;
            int n = e >> 3;
            int kq = e & 7;
            float4 v = make_float4(0.f, 0.f, 0.f, 0.f);
            if ((bn + n) < N)
                v = *reinterpret_cast<const float4*>(&W[(size_t)(bn + n) * ldw + k0 + kq * 4]);
            *reinterpret_cast<float4*>(&sW[n][kq * 4]) = v;
        }
        __syncthreads();

#pragma unroll
        for (int kc = 0; kc < 4; kc++) {
            const int kb = kc * 8;
            uint32_t ahi[2][4], alo[2][4];
#pragma unroll
            for (int mt = 0; mt < 2; mt++) {
                int r0 = wm + mt * 16 + lr;
                float a0 = sA[r0][kb + lc];
                float a1 = sA[r0 + 8][kb + lc];
                float a2 = sA[r0][kb + lc + 4];
                float a3 = sA[r0 + 8][kb + lc + 4];
                tf32_split(a0, ahi[mt][0], alo[mt][0]);
                tf32_split(a1, ahi[mt][1], alo[mt][1]);
                tf32_split(a2, ahi[mt][2], alo[mt][2]);
                tf32_split(a3, ahi[mt][3], alo[mt][3]);
            }
            uint32_t bhi[4][2], blo[4][2];
#pragma unroll
            for (int nt = 0; nt < 4; nt++) {
                int n0 = wn + nt * 8 + lr;
                float b0 = sW[n0][kb + lc];
                float b1 = sW[n0][kb + lc + 4];
                tf32_split(b0, bhi[nt][0], blo[nt][0]);
                tf32_split(b1, bhi[nt][1], blo[nt][1]);
            }
#pragma unroll
            for (int mt = 0; mt < 2; mt++)
#pragma unroll
                for (int nt = 0; nt < 4; nt++) {
                    mma_tf32(acc[mt][nt], ahi[mt], bhi[nt]);
                    mma_tf32(acc[mt][nt], ahi[mt], blo[nt]);
                    mma_tf32(acc[mt][nt], alo[mt], bhi[nt]);
                }
        }
        __syncthreads();
    }

    const float* brow = biasPerRel ? (bias + (size_t)(bm >> 12) * N) : bias;
#pragma unroll
    for (int mt = 0; mt < 2; mt++) {
#pragma unroll
        for (int nt = 0; nt < 4; nt++) {
            int r = bm + wm + mt * 16 + lr;
            int n = bn + wn + nt * 8 + 2 * lc;
            if (n < N) {
                float bsx = brow[n], bsy = brow[n + 1];
                float2 v0 = make_float2(acc[mt][nt][0] + bsx, acc[mt][nt][1] + bsy);
                float2 v1 = make_float2(acc[mt][nt][2] + bsx, acc[mt][nt][3] + bsy);
                if (doRelu) {
                    v0.x = fmaxf(v0.x, 0.f); v0.y = fmaxf(v0.y, 0.f);
                    v1.x = fmaxf(v1.x, 0.f); v1.y = fmaxf(v1.y, 0.f);
                }
                *reinterpret_cast<float2*>(&C[(size_t)r * N + n]) = v0;
                *reinterpret_cast<float2*>(&C[(size_t)(r + 8) * N + n]) = v1;
            }
        }
    }
}

// gsum[b,n] = sum_{r=0..7} X2[r*BSZ + b, n]
__global__ void reduce8_kernel()
{
    int idx = blockIdx.x * 256 + threadIdx.x;
    int b = idx >> 8;
    int n = idx & 255;
    float sum = 0.f;
#pragma unroll
    for (int r = 0; r < 8; r++)
        sum += d_X2[((size_t)(r * BSZ + b)) * GDIM + n];
    d_gsum[idx] = sum;
}

// ---------------------------------------------------------------------------
extern "C" void kernel_launch(void* const* d_in, const int* in_sizes, int n_in,
                              void* d_out, int out_size)
{
    const int*   q    = (const int*)d_in[0];
    SfPtrs sf;
    for (int i = 0; i < 8; i++) sf.p[i] = (const int*)d_in[1 + i];
    const float* emb  = (const float*)d_in[9];
    const float* qWih = (const float*)d_in[10];
    const float* qWhh = (const float*)d_in[11];
    const float* qb   = (const float*)d_in[12];
    const float* sWih = (const float*)d_in[13];
    const float* sWhh = (const float*)d_in[14];
    const float* sb   = (const float*)d_in[15];
    const float* g1W  = (const float*)d_in[16];
    const float* g1b  = (const float*)d_in[17];
    const float* g2W  = (const float*)d_in[18];
    const float* g2b  = (const float*)d_in[19];
    const float* g3W  = (const float*)d_in[20];
    const float* g3b  = (const float*)d_in[21];
    const float* g4W  = (const float*)d_in[22];
    const float* g4b  = (const float*)d_in[23];
    const float* f1W  = (const float*)d_in[24];
    const float* f1b  = (const float*)d_in[25];
    const float* f2W  = (const float*)d_in[26];
    const float* f2b  = (const float*)d_in[27];
    const float* f3W  = (const float*)d_in[28];
    const float* f3b  = (const float*)d_in[29];
    float* out = (float*)d_out;

    void *pX0, *pX1, *pX2, *pGsum, *pY1, *pY2, *pBrel, *pG1w;
    void *pWpkq, *pWpks, *pBpkq, *pBpks, *pXpq, *pXps;
    cudaGetSymbolAddress(&pX0,   d_X0);
    cudaGetSymbolAddress(&pX1,   d_X1);
    cudaGetSymbolAddress(&pX2,   d_X2);
    cudaGetSymbolAddress(&pGsum, d_gsum);
    cudaGetSymbolAddress(&pY1,   d_Y1);
    cudaGetSymbolAddress(&pY2,   d_Y2);
    cudaGetSymbolAddress(&pBrel, d_brel);
    cudaGetSymbolAddress(&pG1w,  d_g1w);
    cudaGetSymbolAddress(&pWpkq, d_wpkq);
    cudaGetSymbolAddress(&pWpks, d_wpks);
    cudaGetSymbolAddress(&pBpkq, d_bpkq);
    cudaGetSymbolAddress(&pBpks, d_bpks);
    cudaGetSymbolAddress(&pXpq,  d_xpq);
    cudaGetSymbolAddress(&pXps,  d_xps);
    const float* X0 = (const float*)pX0;
    float* X1 = (float*)pX1;
    float* X2 = (float*)pX2;
    float* Gs = (float*)pGsum;
    float* Y1 = (float*)pY1;
    float* Y2 = (float*)pY2;
    const float* Brel = (const float*)pBrel;
    const float* G1w  = (const float*)pG1w;

    // 0) repack weights + per-relation g1 bias + dense g1W
    pack_kernel<<<16, 256>>>(qWih, qWhh, qb, sWih, sWhh, sb);
    bias_rel_kernel<<<64, 256>>>(g1W, g1b);

    // 0b) precompute input projections (fp32 GEMM, K=32)
    gemm_kernel<<<dim3(2, VPAD / 128), 256>>>(emb, (const float*)pWpkq, (const float*)pBpkq,
                                              (float*)pXpq, VSIZE, 128, 32, 32, 32, 0, 0);
    gemm_kernel<<<dim3(2, VPAD / 128), 256>>>(emb, (const float*)pWpks, (const float*)pBpks,
                                              (float*)pXps, VSIZE, 128, 32, 32, 32, 0, 0);

    // 1) fused LSTM recurrence (q + 8 sf streams), warp-paired 2 threads/sample
    lstm_kernel<<<NS / 64, 128>>>(q, sf);

    // 2) assemble g1 input [32768, 64]
    build_x0_kernel<<<(NSF + 255) / 256, 256>>>();

    // 3) g-MLP on tensor cores (3xTF32)
    gemm_tc_kernel<<<dim3(GDIM / 64, NSF / 128), 256>>>(X0, G1w, Brel, X1, GDIM, 64, 64, 64, 1, 1);
    gemm_tc_kernel<<<dim3(GDIM / 64, NSF / 128), 256>>>(X1, g2W, g2b, X2, GDIM, GDIM, GDIM, GDIM, 1, 0);
    gemm_tc_kernel<<<dim3(GDIM / 64, NSF / 128), 256>>>(X2, g3W, g3b, X1, GDIM, GDIM, GDIM, GDIM, 1, 0);
    gemm_tc_kernel<<<dim3(GDIM / 64, NSF / 128), 256>>>(X1, g4W, g4b, X2, GDIM, GDIM, GDIM, GDIM, 1, 0);

    // 4) segment-sum over 8 relations
    reduce8_kernel<<<(BSZ * GDIM) / 256, 256>>>();

    // 5) f-head on tensor cores
    gemm_tc_kernel<<<dim3(GDIM / 64,  BSZ / 128), 256>>>(Gs, f1W, f1b, Y1, GDIM,  GDIM,  GDIM,  GDIM,  1, 0);
    gemm_tc_kernel<<<dim3(F2DIM / 64, BSZ / 128), 256>>>(Y1, f2W, f2b, Y2, F2DIM, GDIM,  GDIM,  GDIM,  1, 0);
    gemm_tc_kernel<<<dim3((ADIM + 63) / 64, BSZ / 128), 256>>>(Y2, f3W, f3b, out, ADIM, F2DIM, F2DIM, F2DIM, 0, 0);
}

// round 11
// speedup vs baseline: 1.3666x; 1.3666x over previous
#include <cuda_runtime.h>
#include <cstdint>

// Problem dims
#define BSZ   4096
#define LSEQ  64
#define EDIM  32
#define HDIM  32
#define GDIM  256
#define F2DIM 512
#define ADIM  1000
#define NSF   32768   // 8 * BSZ
#define NS    36864   // 9 * BSZ
#define VSIZE 50000
#define VPAD  50048   // 391 * 128

typedef unsigned long long ull;

// ---------------- scratch (device globals: allocation-free) ----------------
__device__ float d_hq[BSZ * HDIM];                       // [4096, 32]
__device__ float d_X0[(size_t)NSF * 64];                 // [32768, 64]
__device__ float d_X1[(size_t)NSF * GDIM];               // [32768, 256]
__device__ float d_X2[(size_t)NSF * GDIM];               // [32768, 256]
__device__ float d_gsum[(size_t)BSZ * GDIM];             // [4096, 256]
__device__ float d_Y1[(size_t)BSZ * GDIM];               // [4096, 256]
__device__ float d_Y2[(size_t)BSZ * F2DIM];              // [4096, 512]
__device__ float d_brel[8 * GDIM];                       // per-relation g1 bias
__device__ float d_g1w[GDIM * 64];                       // g1W cols 0..63, dense

// Repacked LSTM weights
__device__ float d_wpkq[128 * 32];   // [j4g][e]  from qWih
__device__ float d_wpks[128 * 32];
__device__ float d_bpkq[128];
__device__ float d_bpks[128];
__device__ float d_whhq[32 * 128];   // [j][g*32 + k]  from qWhh
__device__ float d_whhs[32 * 128];

// Precomputed input projections: xproj[v][j*4+g] = Wih·emb[v] + b
__device__ float d_xpq[(size_t)VPAD * 128];
__device__ float d_xps[(size_t)VPAD * 128];

struct SfPtrs { const int* p[8]; };

__device__ __forceinline__ float ftanh_(float x) {
    float r;
    asm("tanh.approx.f32 %0, %1;" : "=f"(r) : "f"(x));
    return r;
}
__device__ __forceinline__ float fsig(float x) {
    return fmaf(ftanh_(0.5f * x), 0.5f, 0.5f);
}
__device__ __forceinline__ ull pack2(float a, float b) {
    ull r; asm("mov.b64 %0, {%1, %2};" : "=l"(r) : "f"(a), "f"(b)); return r;
}
__device__ __forceinline__ float2 unpack2(ull v) {
    float2 r; asm("mov.b64 {%0, %1}, %2;" : "=f"(r.x), "=f"(r.y) : "l"(v)); return r;
}
#define FMA2(acc, a, b) asm("fma.rn.f32x2 %0, %1, %2, %0;" : "+l"(acc) : "l"(a), "l"(b))

__device__ __forceinline__ uint32_t f2tf32(float x) {
    uint32_t r; asm("cvt.rna.tf32.f32 %0, %1;" : "=r"(r) : "f"(x)); return r;
}
__device__ __forceinline__ void tf32_split(float x, uint32_t& hi, uint32_t& lo) {
    hi = f2tf32(x);
    lo = f2tf32(x - __uint_as_float(hi));
}
__device__ __forceinline__ void mma_tf32(float* d, const uint32_t* a, const uint32_t* b) {
    asm volatile(
        "mma.sync.aligned.m16n8k8.row.col.f32.tf32.tf32.f32 "
        "{%0,%1,%2,%3}, {%4,%5,%6,%7}, {%8,%9}, {%0,%1,%2,%3};"
        : "+f"(d[0]), "+f"(d[1]), "+f"(d[2]), "+f"(d[3])
        : "r"(a[0]), "r"(a[1]), "r"(a[2]), "r"(a[3]), "r"(b[0]), "r"(b[1]));
}

// ---------------------------------------------------------------------------
// Repack LSTM weights.
// ---------------------------------------------------------------------------
__global__ void pack_kernel(
    const float* __restrict__ qWih, const float* __restrict__ qWhh, const float* __restrict__ qb,
    const float* __restrict__ sWih, const float* __restrict__ sWhh, const float* __restrict__ sb)
{
    int idx = blockIdx.x * blockDim.x + threadIdx.x;   // 0..4095
    if (idx < 4096) {
        {   // Wih pack: idx = j4g*32 + e
            int j4g = idx >> 5, e = idx & 31;
            int j = j4g >> 2, g = j4g & 3;
            int src = (g * 32 + j) * 32 + e;
            d_wpkq[idx] = qWih[src];
            d_wpks[idx] = sWih[src];
        }
        {   // Whh pack: idx = j*128 + g*32 + k
            int j = idx >> 7, g = (idx >> 5) & 3, k = idx & 31;
            int src = (g * 32 + j) * 32 + k;
            d_whhq[idx] = qWhh[src];
            d_whhs[idx] = sWhh[src];
        }
    }
    if (idx < 128) {
        int j = idx >> 2, g = idx & 3;
        d_bpkq[idx] = qb[g * 32 + j];
        d_bpks[idx] = sb[g * 32 + j];
    }
}

// Per-relation g1 bias + dense g1W repack.
__global__ void bias_rel_kernel(const float* __restrict__ g1W, const float* __restrict__ g1b)
{
    int idx = blockIdx.x * blockDim.x + threadIdx.x;
    if (idx < 8 * GDIM) {
        int r = idx >> 8, n = idx & 255;
        d_brel[idx] = g1b[n] + (float)r * g1W[n * 65 + 64];
    }
    if (idx < GDIM * 64) {
        int n = idx >> 6, k = idx & 63;
        d_g1w[idx] = g1W[n * 65 + k];
    }
}

// ---------------------------------------------------------------------------
// LSTM: thread-per-sample (R8 config) + software-pipelined xproj prefetch.
// 128 samples/block, 288 blocks. Weights broadcast from smem; h/c state in
// thread-private smem columns. xg rows prefetched in groups of 8 (ping-pong
// register buffers) so LDG latency hides under the previous group's FMA2s.
// ---------------------------------------------------------------------------
__global__ __launch_bounds__(128) void lstm_kernel(const int* __restrict__ q, SfPtrs sf)
{
    __shared__ __align__(16) float sWhh[4096];   // packed Whh [j][g*32+k]
    __shared__ __align__(16) float hb[4096];     // [32][128]
    __shared__ __align__(16) float cs[4096];     // [32][128]

    const int tid = threadIdx.x;
    const bool isQ = (blockIdx.x < (BSZ / 128));
    const float* wsrc = isQ ? d_whhq : d_whhs;
    const float* xp   = isQ ? d_xpq  : d_xps;

    for (int i = tid; i < 4096; i += 128) sWhh[i] = wsrc[i];
#pragma unroll
    for (int j = 0; j < 32; j++) {
        hb[j * 128 + tid] = 0.f;
        cs[j * 128 + tid] = 0.f;
    }
    __syncthreads();

    const int s = blockIdx.x * 128 + tid;
    const int* tok;
    int b, ss = 0;
    if (isQ) {
        b = s;
        tok = q + (size_t)b * LSEQ;
    } else {
        ss = s - BSZ;
        int r = ss >> 12;
        b = ss & (BSZ - 1);
        tok = sf.p[r] + (size_t)b * LSEQ;
    }

    for (int t = 0; t < LSEQ; t++) {
        const int token = tok[t];
        const float4* xrow = reinterpret_cast<const float4*>(xp + (size_t)token * 128);

        // previous h -> 16 packed f32x2 registers
        ull h2[16];
#pragma unroll
        for (int k2 = 0; k2 < 16; k2++)
            h2[k2] = pack2(hb[(2 * k2) * 128 + tid], hb[(2 * k2 + 1) * 128 + tid]);

        // software pipeline: prefetch xg in groups of 8 (ping-pong buffers)
        float4 x0[8], x1[8];
#pragma unroll
        for (int i = 0; i < 8; i++) x0[i] = __ldg(&xrow[i]);

#pragma unroll
        for (int grp = 0; grp < 4; grp++) {
            float4* curb = (grp & 1) ? x1 : x0;
            float4* nxtb = (grp & 1) ? x0 : x1;
            if (grp < 3) {
#pragma unroll
                for (int i = 0; i < 8; i++)
                    nxtb[i] = __ldg(&xrow[(grp + 1) * 8 + i]);
            }
#pragma unroll
            for (int jj = 0; jj < 8; jj++) {
                const int j = grp * 8 + jj;
                const float4 xg = curb[jj];
                const ulonglong2* Wj = reinterpret_cast<const ulonglong2*>(sWhh + j * 128);
                ull ai = 0, af = 0, ag = 0, ao = 0;   // bit pattern == {0.f,0.f}
#pragma unroll
                for (int p = 0; p < 8; p++) {
                    ulonglong2 w;
                    w = Wj[p];      FMA2(ai, w.x, h2[2*p]); FMA2(ai, w.y, h2[2*p+1]);
                    w = Wj[8 + p];  FMA2(af, w.x, h2[2*p]); FMA2(af, w.y, h2[2*p+1]);
                    w = Wj[16 + p]; FMA2(ag, w.x, h2[2*p]); FMA2(ag, w.y, h2[2*p+1]);
                    w = Wj[24 + p]; FMA2(ao, w.x, h2[2*p]); FMA2(ao, w.y, h2[2*p+1]);
                }
                float2 vi = unpack2(ai), vf = unpack2(af), vg = unpack2(ag), vo = unpack2(ao);
                const float si  = vi.x + vi.y + xg.x;
                const float sfv = vf.x + vf.y + xg.y;
                const float sg  = vg.x + vg.y + xg.z;
                const float so  = vo.x + vo.y + xg.w;
                float cc = cs[j * 128 + tid];
                cc = fsig(sfv) * cc + fsig(si) * ftanh_(sg);
                cs[j * 128 + tid] = cc;
                hb[j * 128 + tid] = fsig(so) * ftanh_(cc);
            }
        }
    }

    float4* dst = isQ ? reinterpret_cast<float4*>(d_hq + (size_t)b * HDIM)
                      : reinterpret_cast<float4*>(d_X0 + (size_t)ss * 64);
#pragma unroll
    for (int i = 0; i < 8; i++)
        dst[i] = make_float4(hb[(4*i) * 128 + tid], hb[(4*i+1) * 128 + tid],
                             hb[(4*i+2) * 128 + tid], hb[(4*i+3) * 128 + tid]);
}

// X0[s, 32:64] = hq[b]
__global__ void build_x0_kernel()
{
    int s = blockIdx.x * blockDim.x + threadIdx.x;
    if (s >= NSF) return;
    int b = s & (BSZ - 1);
    const float4* src = reinterpret_cast<const float4*>(d_hq + (size_t)b * HDIM);
    float4* dst = reinterpret_cast<float4*>(d_X0 + (size_t)s * 64 + 32);
#pragma unroll
    for (int i = 0; i < 8; i++) dst[i] = src[i];
}

// ---------------------------------------------------------------------------
// fp32 GEMM (double-buffered) — used only for the xproj precompute (K=32).
// ---------------------------------------------------------------------------
__global__ __launch_bounds__(256, 2) void gemm_kernel(
    const float* __restrict__ A, const float* __restrict__ W,
    const float* __restrict__ bias, float* __restrict__ C,
    int Mr, int N, int K, int lda, int ldw, int doRelu, int biasPerRel)
{
    __shared__ __align__(16) float sA[2][16][132];
    __shared__ __align__(16) float sW[2][16][68];

    const int bm = blockIdx.y * 128;
    const int bn = blockIdx.x * 64;
    const int tid = threadIdx.x;
    const int tx = tid & 15;
    const int ty = tid >> 4;

    float acc[8][4];
#pragma unroll
    for (int i = 0; i < 8; i++)
#pragma unroll
        for (int j = 0; j < 4; j++) acc[i][j] = 0.f;

    const int nk = (K + 15) >> 4;

#pragma unroll
    for (int i = 0; i < 8; i++) {
        int e = tid + i * 256; int m = e >> 4; int kk = e & 15;
        sA[0][kk][m] = (kk < K && (bm + m) < Mr) ? A[(size_t)(bm + m) * lda + kk] : 0.f;
    }
#pragma unroll
    for (int i = 0; i < 4; i++) {
        int e = tid + i * 256; int n = e >> 4; int kk = e & 15;
        sW[0][kk][n] = (kk < K && (bn + n) < N) ? W[(size_t)(bn + n) * ldw + kk] : 0.f;
    }
    __syncthreads();

    for (int kt = 0; kt < nk; kt++) {
        const int cur = kt & 1;
        float pa[8], pw[4];
        const bool has = (kt + 1 < nk);
        if (has) {
            int k0 = (kt + 1) << 4;
#pragma unroll
            for (int i = 0; i < 8; i++) {
                int e = tid + i * 256; int m = e >> 4; int kk = e & 15; int gk = k0 + kk;
                pa[i] = (gk < K && (bm + m) < Mr) ? A[(size_t)(bm + m) * lda + gk] : 0.f;
            }
#pragma unroll
            for (int i = 0; i < 4; i++) {
                int e = tid + i * 256; int n = e >> 4; int kk = e & 15; int gk = k0 + kk;
                pw[i] = (gk < K && (bn + n) < N) ? W[(size_t)(bn + n) * ldw + gk] : 0.f;
            }
        }
#pragma unroll
        for (int kk = 0; kk < 16; kk++) {
            float a[8], w[4];
            float4 a0 = *reinterpret_cast<const float4*>(&sA[cur][kk][ty * 8]);
            float4 a1 = *reinterpret_cast<const float4*>(&sA[cur][kk][ty * 8 + 4]);
            float4 w0 = *reinterpret_cast<const float4*>(&sW[cur][kk][tx * 4]);
            a[0]=a0.x; a[1]=a0.y; a[2]=a0.z; a[3]=a0.w;
            a[4]=a1.x; a[5]=a1.y; a[6]=a1.z; a[7]=a1.w;
            w[0]=w0.x; w[1]=w0.y; w[2]=w0.z; w[3]=w0.w;
#pragma unroll
            for (int i = 0; i < 8; i++)
#pragma unroll
                for (int j = 0; j < 4; j++) acc[i][j] += a[i] * w[j];
        }
        if (has) {
            const int nxt = cur ^ 1;
#pragma unroll
            for (int i = 0; i < 8; i++) {
                int e = tid + i * 256; int m = e >> 4; int kk = e & 15;
                sA[nxt][kk][m] = pa[i];
            }
#pragma unroll
            for (int i = 0; i < 4; i++) {
                int e = tid + i * 256; int n = e >> 4; int kk = e & 15;
                sW[nxt][kk][n] = pw[i];
            }
            __syncthreads();
        }
    }

    const float* brow = biasPerRel ? (bias + (size_t)(bm >> 12) * N) : bias;
#pragma unroll
    for (int i = 0; i < 8; i++) {
        int m = bm + ty * 8 + i;
#pragma unroll
        for (int j = 0; j < 4; j++) {
            int n = bn + tx * 4 + j;
            if (n < N) {
                float v = acc[i][j] + brow[n];
                if (doRelu) v = fmaxf(v, 0.f);
                C[(size_t)m * N + n] = v;
            }
        }
    }
}

// ---------------------------------------------------------------------------
// 3xTF32 tensor-core GEMM (single-buffered, static smem — R8 known-good).
// C[M,N] = act(A[M,K(lda)] @ W[N,K(ldw)]^T + bias)
// Requirements: M % 128 == 0, K % 32 == 0, lda % 4 == 0, ldw % 4 == 0.
// ---------------------------------------------------------------------------
__global__ __launch_bounds__(256) void gemm_tc_kernel(
    const float* __restrict__ A, const float* __restrict__ W,
    const float* __restrict__ bias, float* __restrict__ C,
    int N, int K, int lda, int ldw, int doRelu, int biasPerRel)
{
    __shared__ __align__(16) float sA[128][36];
    __shared__ __align__(16) float sW[64][36];

    const int bm = blockIdx.y * 128;
    const int bn = blockIdx.x * 64;
    const int tid  = threadIdx.x;
    const int lane = tid & 31;
    const int wid  = tid >> 5;
    const int warpM = wid & 3;
    const int warpN = wid >> 2;
    const int wm = warpM * 32;
    const int wn = warpN * 32;
    const int lr = lane >> 2;
    const int lc = lane & 3;

    float acc[2][4][4];
#pragma unroll
    for (int mt = 0; mt < 2; mt++)
#pragma unroll
        for (int nt = 0; nt < 4; nt++)
#pragma unroll
            for (int r = 0; r < 4; r++) acc[mt][nt][r] = 0.f;

    for (int k0 = 0; k0 < K; k0 += 32) {
#pragma unroll
        for (int i = 0; i < 4; i++) {
            int e = tid + i * 256;
            int m = e >> 3;
            int kq = e & 7;
            float4 v = *reinterpret_cast<const float4*>(&A[(size_t)(bm + m) * lda + k0 + kq * 4]);
            *reinterpret_cast<float4*>(&sA[m][kq * 4]) = v;
        }
#pragma unroll
        for (int i = 0; i < 2; i++) {
            int e = tid + i * 256;
            int n = e >> 3;
            int kq = e & 7;
            float4 v = make_float4(0.f, 0.f, 0.f, 0.f);
            if ((bn + n) < N)
                v = *reinterpret_cast<const float4*>(&W[(size_t)(bn + n) * ldw + k0 + kq * 4]);
            *reinterpret_cast<float4*>(&sW[n][kq * 4]) = v;
        }
        __syncthreads();

#pragma unroll
        for (int kc = 0; kc < 4; kc++) {
            const int kb = kc * 8;
            uint32_t ahi[2][4], alo[2][4];
#pragma unroll
            for (int mt = 0; mt < 2; mt++) {
                int r0 = wm + mt * 16 + lr;
                float a0 = sA[r0][kb + lc];
                float a1 = sA[r0 + 8][kb + lc];
                float a2 = sA[r0][kb + lc + 4];
                float a3 = sA[r0 + 8][kb + lc + 4];
                tf32_split(a0, ahi[mt][0], alo[mt][0]);
                tf32_split(a1, ahi[mt][1], alo[mt][1]);
                tf32_split(a2, ahi[mt][2], alo[mt][2]);
                tf32_split(a3, ahi[mt][3], alo[mt][3]);
            }
            uint32_t bhi[4][2], blo[4][2];
#pragma unroll
            for (int nt = 0; nt < 4; nt++) {
                int n0 = wn + nt * 8 + lr;
                float b0 = sW[n0][kb + lc];
                float b1 = sW[n0][kb + lc + 4];
                tf32_split(b0, bhi[nt][0], blo[nt][0]);
                tf32_split(b1, bhi[nt][1], blo[nt][1]);
            }
#pragma unroll
            for (int mt = 0; mt < 2; mt++)
#pragma unroll
                for (int nt = 0; nt < 4; nt++) {
                    mma_tf32(acc[mt][nt], ahi[mt], bhi[nt]);
                    mma_tf32(acc[mt][nt], ahi[mt], blo[nt]);
                    mma_tf32(acc[mt][nt], alo[mt], bhi[nt]);
                }
        }
        __syncthreads();
    }

    const float* brow = biasPerRel ? (bias + (size_t)(bm >> 12) * N) : bias;
#pragma unroll
    for (int mt = 0; mt < 2; mt++) {
#pragma unroll
        for (int nt = 0; nt < 4; nt++) {
            int r = bm + wm + mt * 16 + lr;
            int n = bn + wn + nt * 8 + 2 * lc;
            if (n < N) {
                float bsx = brow[n], bsy = brow[n + 1];
                float2 v0 = make_float2(acc[mt][nt][0] + bsx, acc[mt][nt][1] + bsy);
                float2 v1 = make_float2(acc[mt][nt][2] + bsx, acc[mt][nt][3] + bsy);
                if (doRelu) {
                    v0.x = fmaxf(v0.x, 0.f); v0.y = fmaxf(v0.y, 0.f);
                    v1.x = fmaxf(v1.x, 0.f); v1.y = fmaxf(v1.y, 0.f);
                }
                *reinterpret_cast<float2*>(&C[(size_t)r * N + n]) = v0;
                *reinterpret_cast<float2*>(&C[(size_t)(r + 8) * N + n]) = v1;
            }
        }
    }
}

// gsum[b,n] = sum_{r=0..7} X2[r*BSZ + b, n]
__global__ void reduce8_kernel()
{
    int idx = blockIdx.x * 256 + threadIdx.x;
    int b = idx >> 8;
    int n = idx & 255;
    float sum = 0.f;
#pragma unroll
    for (int r = 0; r < 8; r++)
        sum += d_X2[((size_t)(r * BSZ + b)) * GDIM + n];
    d_gsum[idx] = sum;
}

// ---------------------------------------------------------------------------
extern "C" void kernel_launch(void* const* d_in, const int* in_sizes, int n_in,
                              void* d_out, int out_size)
{
    const int*   q    = (const int*)d_in[0];
    SfPtrs sf;
    for (int i = 0; i < 8; i++) sf.p[i] = (const int*)d_in[1 + i];
    const float* emb  = (const float*)d_in[9];
    const float* qWih = (const float*)d_in[10];
    const float* qWhh = (const float*)d_in[11];
    const float* qb   = (const float*)d_in[12];
    const float* sWih = (const float*)d_in[13];
    const float* sWhh = (const float*)d_in[14];
    const float* sb   = (const float*)d_in[15];
    const float* g1W  = (const float*)d_in[16];
    const float* g1b  = (const float*)d_in[17];
    const float* g2W  = (const float*)d_in[18];
    const float* g2b  = (const float*)d_in[19];
    const float* g3W  = (const float*)d_in[20];
    const float* g3b  = (const float*)d_in[21];
    const float* g4W  = (const float*)d_in[22];
    const float* g4b  = (const float*)d_in[23];
    const float* f1W  = (const float*)d_in[24];
    const float* f1b  = (const float*)d_in[25];
    const float* f2W  = (const float*)d_in[26];
    const float* f2b  = (const float*)d_in[27];
    const float* f3W  = (const float*)d_in[28];
    const float* f3b  = (const float*)d_in[29];
    float* out = (float*)d_out;

    void *pX0, *pX1, *pX2, *pGsum, *pY1, *pY2, *pBrel, *pG1w;
    void *pWpkq, *pWpks, *pBpkq, *pBpks, *pXpq, *pXps;
    cudaGetSymbolAddress(&pX0,   d_X0);
    cudaGetSymbolAddress(&pX1,   d_X1);
    cudaGetSymbolAddress(&pX2,   d_X2);
    cudaGetSymbolAddress(&pGsum, d_gsum);
    cudaGetSymbolAddress(&pY1,   d_Y1);
    cudaGetSymbolAddress(&pY2,   d_Y2);
    cudaGetSymbolAddress(&pBrel, d_brel);
    cudaGetSymbolAddress(&pG1w,  d_g1w);
    cudaGetSymbolAddress(&pWpkq, d_wpkq);
    cudaGetSymbolAddress(&pWpks, d_wpks);
    cudaGetSymbolAddress(&pBpkq, d_bpkq);
    cudaGetSymbolAddress(&pBpks, d_bpks);
    cudaGetSymbolAddress(&pXpq,  d_xpq);
    cudaGetSymbolAddress(&pXps,  d_xps);
    const float* X0 = (const float*)pX0;
    float* X1 = (float*)pX1;
    float* X2 = (float*)pX2;
    float* Gs = (float*)pGsum;
    float* Y1 = (float*)pY1;
    float* Y2 = (float*)pY2;
    const float* Brel = (const float*)pBrel;
    const float* G1w  = (const float*)pG1w;

    // 0) repack weights + per-relation g1 bias + dense g1W
    pack_kernel<<<16, 256>>>(qWih, qWhh, qb, sWih, sWhh, sb);
    bias_rel_kernel<<<64, 256>>>(g1W, g1b);

    // 0b) precompute input projections (fp32 GEMM, K=32)
    gemm_kernel<<<dim3(2, VPAD / 128), 256>>>(emb, (const float*)pWpkq, (const float*)pBpkq,
                                              (float*)pXpq, VSIZE, 128, 32, 32, 32, 0, 0);
    gemm_kernel<<<dim3(2, VPAD / 128), 256>>>(emb, (const float*)pWpks, (const float*)pBpks,
                                              (float*)pXps, VSIZE, 128, 32, 32, 32, 0, 0);

    // 1) fused LSTM recurrence (q + 8 sf streams), thread-per-sample + prefetch
    lstm_kernel<<<NS / 128, 128>>>(q, sf);

    // 2) assemble g1 input [32768, 64]
    build_x0_kernel<<<(NSF + 255) / 256, 256>>>();

    // 3) g-MLP on tensor cores (3xTF32)
    gemm_tc_kernel<<<dim3(GDIM / 64, NSF / 128), 256>>>(X0, G1w, Brel, X1, GDIM, 64, 64, 64, 1, 1);
    gemm_tc_kernel<<<dim3(GDIM / 64, NSF / 128), 256>>>(X1, g2W, g2b, X2, GDIM, GDIM, GDIM, GDIM, 1, 0);
    gemm_tc_kernel<<<dim3(GDIM / 64, NSF / 128), 256>>>(X2, g3W, g3b, X1, GDIM, GDIM, GDIM, GDIM, 1, 0);
    gemm_tc_kernel<<<dim3(GDIM / 64, NSF / 128), 256>>>(X1, g4W, g4b, X2, GDIM, GDIM, GDIM, GDIM, 1, 0);

    // 4) segment-sum over 8 relations
    reduce8_kernel<<<(BSZ * GDIM) / 256, 256>>>();

    // 5) f-head on tensor cores
    gemm_tc_kernel<<<dim3(GDIM / 64,  BSZ / 128), 256>>>(Gs, f1W, f1b, Y1, GDIM,  GDIM,  GDIM,  GDIM,  1, 0);
    gemm_tc_kernel<<<dim3(F2DIM / 64, BSZ / 128), 256>>>(Y1, f2W, f2b, Y2, F2DIM, GDIM,  GDIM,  GDIM,  1, 0);
    gemm_tc_kernel<<<dim3((ADIM + 63) / 64, BSZ / 128), 256>>>(Y2, f3W, f3b, out, ADIM, F2DIM, F2DIM, F2DIM, 0, 0);
}

// round 12
// speedup vs baseline: 2.0273x; 1.4834x over previous
#include <cuda_runtime.h>
#include <cstdint>

// Problem dims
#define BSZ   4096
#define LSEQ  64
#define EDIM  32
#define HDIM  32
#define GDIM  256
#define F2DIM 512
#define ADIM  1000
#define NSF   32768   // 8 * BSZ
#define NS    36864   // 9 * BSZ
#define VSIZE 50000
#define VPAD  50048   // 391 * 128

typedef unsigned long long ull;

// ---------------- scratch (device globals: allocation-free) ----------------
__device__ float d_hq[BSZ * HDIM];                       // [4096, 32]
__device__ float d_X0[(size_t)NSF * 64];                 // [32768, 64]
__device__ float d_X1[(size_t)NSF * GDIM];               // [32768, 256]
__device__ float d_X2[(size_t)NSF * GDIM];               // [32768, 256]
__device__ float d_gsum[(size_t)BSZ * GDIM];             // [4096, 256]
__device__ float d_Y1[(size_t)BSZ * GDIM];               // [4096, 256]
__device__ float d_Y2[(size_t)BSZ * F2DIM];              // [4096, 512]
__device__ float d_brel[8 * GDIM];                       // per-relation g1 bias
__device__ float d_g1w[GDIM * 64];                       // g1W cols 0..63, dense

// Pre-split Whh for tensor-core LSTM: [n=g*32+j][k], padded to 36, (hi,lo) tf32
__device__ uint2 d_whhpkq[128 * 36];
__device__ uint2 d_whhpks[128 * 36];

// Precomputed input projections: xproj[v][n = g*32+j] = Wih·emb[v] + b  (native layout)
__device__ float d_xpq[(size_t)VPAD * 128];
__device__ float d_xps[(size_t)VPAD * 128];

struct SfPtrs { const int* p[8]; };

__device__ __forceinline__ float ftanh_(float x) {
    float r;
    asm("tanh.approx.f32 %0, %1;" : "=f"(r) : "f"(x));
    return r;
}
__device__ __forceinline__ float fsig(float x) {
    return fmaf(ftanh_(0.5f * x), 0.5f, 0.5f);
}
__device__ __forceinline__ uint32_t f2tf32(float x) {
    uint32_t r; asm("cvt.rna.tf32.f32 %0, %1;" : "=r"(r) : "f"(x)); return r;
}
__device__ __forceinline__ void tf32_split(float x, uint32_t& hi, uint32_t& lo) {
    hi = f2tf32(x);
    lo = f2tf32(x - __uint_as_float(hi));
}
__device__ __forceinline__ void mma_tf32(float* d, const uint32_t* a, const uint32_t* b) {
    asm volatile(
        "mma.sync.aligned.m16n8k8.row.col.f32.tf32.tf32.f32 "
        "{%0,%1,%2,%3}, {%4,%5,%6,%7}, {%8,%9}, {%0,%1,%2,%3};"
        : "+f"(d[0]), "+f"(d[1]), "+f"(d[2]), "+f"(d[3])
        : "r"(a[0]), "r"(a[1]), "r"(a[2]), "r"(a[3]), "r"(b[0]), "r"(b[1]));
}

// ---------------------------------------------------------------------------
// Pack Whh into pre-split tf32 (hi,lo) with row pad 36. Native row order
// n = g*32+j (torch layout). Pads zeroed.
// ---------------------------------------------------------------------------
__global__ void pack_kernel(const float* __restrict__ qWhh, const float* __restrict__ sWhh)
{
    int idx = blockIdx.x * blockDim.x + threadIdx.x;   // 0 .. 128*36-1
    if (idx < 128 * 36) {
        int n = idx / 36, k = idx % 36;
        float vq = (k < 32) ? qWhh[n * 32 + k] : 0.f;
        float vs = (k < 32) ? sWhh[n * 32 + k] : 0.f;
        uint32_t hi, lo;
        tf32_split(vq, hi, lo);
        d_whhpkq[idx] = make_uint2(hi, lo);
        tf32_split(vs, hi, lo);
        d_whhpks[idx] = make_uint2(hi, lo);
    }
}

// Per-relation g1 bias + dense g1W repack.
__global__ void bias_rel_kernel(const float* __restrict__ g1W, const float* __restrict__ g1b)
{
    int idx = blockIdx.x * blockDim.x + threadIdx.x;
    if (idx < 8 * GDIM) {
        int r = idx >> 8, n = idx & 255;
        d_brel[idx] = g1b[n] + (float)r * g1W[n * 65 + 64];
    }
    if (idx < GDIM * 64) {
        int n = idx >> 6, k = idx & 63;
        d_g1w[idx] = g1W[n * 65 + k];
    }
}

// ---------------------------------------------------------------------------
// Tensor-core LSTM recurrence. Block = 64 samples, 128 threads (4 warps),
// warp owns 16 sample rows. Per step: G[16 x 128gates] = h·Whh^T + xproj via
// m16n8k8 3xTF32 mma; gates order n = g*32+j puts all 4 gates of (s,j) in the
// SAME lane -> c update lane-local, c in registers. h round-trips through
// warp-private smem rows pre-split to tf32 hi/lo. NO __syncthreads in loop.
// ---------------------------------------------------------------------------
#define LSTM_SMEM_BYTES ((128 * 36 + 64 * 36) * 8)   // 55296 B

__global__ void __launch_bounds__(128, 3) lstm_tc_kernel(const int* __restrict__ q, SfPtrs sf)
{
    extern __shared__ uint2 sm2[];
    uint2* sWhh = sm2;              // [128][36]
    uint2* sH   = sm2 + 128 * 36;   // [64][36]

    const int tid  = threadIdx.x;
    const int lane = tid & 31;
    const int wm   = (tid >> 5) * 16;   // warp's first local sample row
    const int lr   = lane >> 2;         // 0..7
    const int lc   = lane & 3;          // 0..3

    const bool isQ = (blockIdx.x < (BSZ / 64));
    const uint2* wsrc = isQ ? d_whhpkq : d_whhpks;
    const float* xp   = isQ ? d_xpq    : d_xps;

    for (int i = tid; i < 128 * 36; i += 128) sWhh[i] = wsrc[i];
    for (int i = tid; i < 64 * 36; i += 128) sH[i] = make_uint2(0u, 0u);
    __syncthreads();

    // this lane's two sample rows (local wm+lr, wm+lr+8)
    const int s0 = blockIdx.x * 64 + wm + lr;
    const int s1 = s0 + 8;
    const int *pt0, *pt1;
    if (isQ) {
        pt0 = q + (size_t)s0 * LSEQ;
        pt1 = q + (size_t)s1 * LSEQ;
    } else {
        int ss0 = s0 - BSZ;
        int r = ss0 >> 12;                       // same relation for whole block
        pt0 = sf.p[r] + (size_t)(ss0 & (BSZ - 1)) * LSEQ;
        pt1 = sf.p[r] + (size_t)((s1 - BSZ) & (BSZ - 1)) * LSEQ;
    }

    float c[16];
#pragma unroll
    for (int i = 0; i < 16; i++) c[i] = 0.f;

    for (int t = 0; t < LSEQ; t++) {
        const int tok0 = __ldg(&pt0[t]);
        const int tok1 = __ldg(&pt1[t]);
        const float2* xr0 = reinterpret_cast<const float2*>(xp + (size_t)tok0 * 128);
        const float2* xr1 = reinterpret_cast<const float2*>(xp + (size_t)tok1 * 128);

        // acc init = xproj (includes bias); col for acc[nt][0] = nt*8 + 2*lc
        float acc[16][4];
#pragma unroll
        for (int nt = 0; nt < 16; nt++) {
            float2 g0 = __ldg(&xr0[nt * 4 + lc]);
            float2 g1 = __ldg(&xr1[nt * 4 + lc]);
            acc[nt][0] = g0.x; acc[nt][1] = g0.y;
            acc[nt][2] = g1.x; acc[nt][3] = g1.y;
        }

        // mma: G += h @ Whh^T  (3xTF32)
#pragma unroll
        for (int kc = 0; kc < 4; kc++) {
            const int kb = kc * 8;
            const uint2 a0 = sH[(wm + lr) * 36 + kb + lc];
            const uint2 a1 = sH[(wm + lr + 8) * 36 + kb + lc];
            const uint2 a2 = sH[(wm + lr) * 36 + kb + lc + 4];
            const uint2 a3 = sH[(wm + lr + 8) * 36 + kb + lc + 4];
            const uint32_t ah[4] = { a0.x, a1.x, a2.x, a3.x };
            const uint32_t al[4] = { a0.y, a1.y, a2.y, a3.y };
#pragma unroll
            for (int nt = 0; nt < 16; nt++) {
                const uint2 b0 = sWhh[(nt * 8 + lr) * 36 + kb + lc];
                const uint2 b1 = sWhh[(nt * 8 + lr) * 36 + kb + lc + 4];
                const uint32_t bh[2] = { b0.x, b1.x };
                const uint32_t bl[2] = { b0.y, b1.y };
                mma_tf32(acc[nt], ah, bh);
                mma_tf32(acc[nt], ah, bl);
                mma_tf32(acc[nt], al, bh);
            }
        }

        // epilogue: gate g of (s,j) lives at acc[g*4 + qx][cix],
        // j = qx*8 + 2*lc + (cix&1), row = wm + lr + (cix>>1)*8
#pragma unroll
        for (int qx = 0; qx < 4; qx++) {
#pragma unroll
            for (int cix = 0; cix < 4; cix++) {
                const float gi = acc[0 * 4 + qx][cix];
                const float gf = acc[1 * 4 + qx][cix];
                const float gg = acc[2 * 4 + qx][cix];
                const float go = acc[3 * 4 + qx][cix];
                const int idx = qx * 4 + cix;
                float cc = c[idx];
                cc = fsig(gf) * cc + fsig(gi) * ftanh_(gg);
                c[idx] = cc;
                const float hv = fsig(go) * ftanh_(cc);
                uint32_t hi, lo;
                tf32_split(hv, hi, lo);
                const int row = wm + lr + (cix >> 1) * 8;
                const int k   = qx * 8 + 2 * lc + (cix & 1);
                sH[row * 36 + k] = make_uint2(hi, lo);
            }
        }
        __syncwarp();
    }

    // write out final h: lane handles row wm + (lane>>1), k-half (lane&1)*16
    {
        const int rl = wm + (lane >> 1);
        const int kb = (lane & 1) * 16;
        float hv[16];
#pragma unroll
        for (int i = 0; i < 16; i++) {
            uint2 v = sH[rl * 36 + kb + i];
            hv[i] = __uint_as_float(v.x) + __uint_as_float(v.y);
        }
        const int sg = blockIdx.x * 64 + rl;
        float* dst = isQ ? (d_hq + (size_t)sg * HDIM + kb)
                         : (d_X0 + (size_t)(sg - BSZ) * 64 + kb);
        float4* d4 = reinterpret_cast<float4*>(dst);
#pragma unroll
        for (int i = 0; i < 4; i++)
            d4[i] = make_float4(hv[4 * i], hv[4 * i + 1], hv[4 * i + 2], hv[4 * i + 3]);
    }
}

// X0[s, 32:64] = hq[b]
__global__ void build_x0_kernel()
{
    int s = blockIdx.x * blockDim.x + threadIdx.x;
    if (s >= NSF) return;
    int b = s & (BSZ - 1);
    const float4* src = reinterpret_cast<const float4*>(d_hq + (size_t)b * HDIM);
    float4* dst = reinterpret_cast<float4*>(d_X0 + (size_t)s * 64 + 32);
#pragma unroll
    for (int i = 0; i < 8; i++) dst[i] = src[i];
}

// ---------------------------------------------------------------------------
// fp32 GEMM (double-buffered) — used only for the xproj precompute (K=32).
// ---------------------------------------------------------------------------
__global__ __launch_bounds__(256, 2) void gemm_kernel(
    const float* __restrict__ A, const float* __restrict__ W,
    const float* __restrict__ bias, float* __restrict__ C,
    int Mr, int N, int K, int lda, int ldw, int doRelu, int biasPerRel)
{
    __shared__ __align__(16) float sA[2][16][132];
    __shared__ __align__(16) float sW[2][16][68];

    const int bm = blockIdx.y * 128;
    const int bn = blockIdx.x * 64;
    const int tid = threadIdx.x;
    const int tx = tid & 15;
    const int ty = tid >> 4;

    float acc[8][4];
#pragma unroll
    for (int i = 0; i < 8; i++)
#pragma unroll
        for (int j = 0; j < 4; j++) acc[i][j] = 0.f;

    const int nk = (K + 15) >> 4;

#pragma unroll
    for (int i = 0; i < 8; i++) {
        int e = tid + i * 256; int m = e >> 4; int kk = e & 15;
        sA[0][kk][m] = (kk < K && (bm + m) < Mr) ? A[(size_t)(bm + m) * lda + kk] : 0.f;
    }
#pragma unroll
    for (int i = 0; i < 4; i++) {
        int e = tid + i * 256; int n = e >> 4; int kk = e & 15;
        sW[0][kk][n] = (kk < K && (bn + n) < N) ? W[(size_t)(bn + n) * ldw + kk] : 0.f;
    }
    __syncthreads();

    for (int kt = 0; kt < nk; kt++) {
        const int cur = kt & 1;
        float pa[8], pw[4];
        const bool has = (kt + 1 < nk);
        if (has) {
            int k0 = (kt + 1) << 4;
#pragma unroll
            for (int i = 0; i < 8; i++) {
                int e = tid + i * 256; int m = e >> 4; int kk = e & 15; int gk = k0 + kk;
                pa[i] = (gk < K && (bm + m) < Mr) ? A[(size_t)(bm + m) * lda + gk] : 0.f;
            }
#pragma unroll
            for (int i = 0; i < 4; i++) {
                int e = tid + i * 256; int n = e >> 4; int kk = e & 15; int gk = k0 + kk;
                pw[i] = (gk < K && (bn + n) < N) ? W[(size_t)(bn + n) * ldw + gk] : 0.f;
            }
        }
#pragma unroll
        for (int kk = 0; kk < 16; kk++) {
            float a[8], w[4];
            float4 a0 = *reinterpret_cast<const float4*>(&sA[cur][kk][ty * 8]);
            float4 a1 = *reinterpret_cast<const float4*>(&sA[cur][kk][ty * 8 + 4]);
            float4 w0 = *reinterpret_cast<const float4*>(&sW[cur][kk][tx * 4]);
            a[0]=a0.x; a[1]=a0.y; a[2]=a0.z; a[3]=a0.w;
            a[4]=a1.x; a[5]=a1.y; a[6]=a1.z; a[7]=a1.w;
            w[0]=w0.x; w[1]=w0.y; w[2]=w0.z; w[3]=w0.w;
#pragma unroll
            for (int i = 0; i < 8; i++)
#pragma unroll
                for (int j = 0; j < 4; j++) acc[i][j] += a[i] * w[j];
        }
        if (has) {
            const int nxt = cur ^ 1;
#pragma unroll
            for (int i = 0; i < 8; i++) {
                int e = tid + i * 256; int m = e >> 4; int kk = e & 15;
                sA[nxt][kk][m] = pa[i];
            }
#pragma unroll
            for (int i = 0; i < 4; i++) {
                int e = tid + i * 256; int n = e >> 4; int kk = e & 15;
                sW[nxt][kk][n] = pw[i];
            }
            __syncthreads();
        }
    }

    const float* brow = biasPerRel ? (bias + (size_t)(bm >> 12) * N) : bias;
#pragma unroll
    for (int i = 0; i < 8; i++) {
        int m = bm + ty * 8 + i;
#pragma unroll
        for (int j = 0; j < 4; j++) {
            int n = bn + tx * 4 + j;
            if (n < N) {
                float v = acc[i][j] + brow[n];
                if (doRelu) v = fmaxf(v, 0.f);
                C[(size_t)m * N + n] = v;
            }
        }
    }
}

// ---------------------------------------------------------------------------
// 3xTF32 tensor-core GEMM (single-buffered, static smem — known-good).
// ---------------------------------------------------------------------------
__global__ __launch_bounds__(256) void gemm_tc_kernel(
    const float* __restrict__ A, const float* __restrict__ W,
    const float* __restrict__ bias, float* __restrict__ C,
    int N, int K, int lda, int ldw, int doRelu, int biasPerRel)
{
    __shared__ __align__(16) float sA[128][36];
    __shared__ __align__(16) float sW[64][36];

    const int bm = blockIdx.y * 128;
    const int bn = blockIdx.x * 64;
    const int tid  = threadIdx.x;
    const int lane = tid & 31;
    const int wid  = tid >> 5;
    const int warpM = wid & 3;
    const int warpN = wid >> 2;
    const int wm = warpM * 32;
    const int wn = warpN * 32;
    const int lr = lane >> 2;
    const int lc = lane & 3;

    float acc[2][4][4];
#pragma unroll
    for (int mt = 0; mt < 2; mt++)
#pragma unroll
        for (int nt = 0; nt < 4; nt++)
#pragma unroll
            for (int r = 0; r < 4; r++) acc[mt][nt][r] = 0.f;

    for (int k0 = 0; k0 < K; k0 += 32) {
#pragma unroll
        for (int i = 0; i < 4; i++) {
            int e = tid + i * 256;
            int m = e >> 3;
            int kq = e & 7;
            float4 v = *reinterpret_cast<const float4*>(&A[(size_t)(bm + m) * lda + k0 + kq * 4]);
            *reinterpret_cast<float4*>(&sA[m][kq * 4]) = v;
        }
#pragma unroll
        for (int i = 0; i < 2; i++) {
            int e = tid + i * 256;
            int n = e >> 3;
            int kq = e & 7;
            float4 v = make_float4(0.f, 0.f, 0.f, 0.f);
            if ((bn + n) < N)
                v = *reinterpret_cast<const float4*>(&W[(size_t)(bn + n) * ldw + k0 + kq * 4]);
            *reinterpret_cast<float4*>(&sW[n][kq * 4]) = v;
        }
        __syncthreads();

#pragma unroll
        for (int kc = 0; kc < 4; kc++) {
            const int kb = kc * 8;
            uint32_t ahi[2][4], alo[2][4];
#pragma unroll
            for (int mt = 0; mt < 2; mt++) {
                int r0 = wm + mt * 16 + lr;
                float a0 = sA[r0][kb + lc];
                float a1 = sA[r0 + 8][kb + lc];
                float a2 = sA[r0][kb + lc + 4];
                float a3 = sA[r0 + 8][kb + lc + 4];
                tf32_split(a0, ahi[mt][0], alo[mt][0]);
                tf32_split(a1, ahi[mt][1], alo[mt][1]);
                tf32_split(a2, ahi[mt][2], alo[mt][2]);
                tf32_split(a3, ahi[mt][3], alo[mt][3]);
            }
            uint32_t bhi[4][2], blo[4][2];
#pragma unroll
            for (int nt = 0; nt < 4; nt++) {
                int n0 = wn + nt * 8 + lr;
                float b0 = sW[n0][kb + lc];
                float b1 = sW[n0][kb + lc + 4];
                tf32_split(b0, bhi[nt][0], blo[nt][0]);
                tf32_split(b1, bhi[nt][1], blo[nt][1]);
            }
#pragma unroll
            for (int mt = 0; mt < 2; mt++)
#pragma unroll
                for (int nt = 0; nt < 4; nt++) {
                    mma_tf32(acc[mt][nt], ahi[mt], bhi[nt]);
                    mma_tf32(acc[mt][nt], ahi[mt], blo[nt]);
                    mma_tf32(acc[mt][nt], alo[mt], bhi[nt]);
                }
        }
        __syncthreads();
    }

    const float* brow = biasPerRel ? (bias + (size_t)(bm >> 12) * N) : bias;
#pragma unroll
    for (int mt = 0; mt < 2; mt++) {
#pragma unroll
        for (int nt = 0; nt < 4; nt++) {
            int r = bm + wm + mt * 16 + lr;
            int n = bn + wn + nt * 8 + 2 * lc;
            if (n < N) {
                float bsx = brow[n], bsy = brow[n + 1];
                float2 v0 = make_float2(acc[mt][nt][0] + bsx, acc[mt][nt][1] + bsy);
                float2 v1 = make_float2(acc[mt][nt][2] + bsx, acc[mt][nt][3] + bsy);
                if (doRelu) {
                    v0.x = fmaxf(v0.x, 0.f); v0.y = fmaxf(v0.y, 0.f);
                    v1.x = fmaxf(v1.x, 0.f); v1.y = fmaxf(v1.y, 0.f);
                }
                *reinterpret_cast<float2*>(&C[(size_t)r * N + n]) = v0;
                *reinterpret_cast<float2*>(&C[(size_t)(r + 8) * N + n]) = v1;
            }
        }
    }
}

// gsum[b,n] = sum_{r=0..7} X2[r*BSZ + b, n]
__global__ void reduce8_kernel()
{
    int idx = blockIdx.x * 256 + threadIdx.x;
    int b = idx >> 8;
    int n = idx & 255;
    float sum = 0.f;
#pragma unroll
    for (int r = 0; r < 8; r++)
        sum += d_X2[((size_t)(r * BSZ + b)) * GDIM + n];
    d_gsum[idx] = sum;
}

// ---------------------------------------------------------------------------
extern "C" void kernel_launch(void* const* d_in, const int* in_sizes, int n_in,
                              void* d_out, int out_size)
{
    const int*   q    = (const int*)d_in[0];
    SfPtrs sf;
    for (int i = 0; i < 8; i++) sf.p[i] = (const int*)d_in[1 + i];
    const float* emb  = (const float*)d_in[9];
    const float* qWih = (const float*)d_in[10];
    const float* qWhh = (const float*)d_in[11];
    const float* qb   = (const float*)d_in[12];
    const float* sWih = (const float*)d_in[13];
    const float* sWhh = (const float*)d_in[14];
    const float* sb   = (const float*)d_in[15];
    const float* g1W  = (const float*)d_in[16];
    const float* g1b  = (const float*)d_in[17];
    const float* g2W  = (const float*)d_in[18];
    const float* g2b  = (const float*)d_in[19];
    const float* g3W  = (const float*)d_in[20];
    const float* g3b  = (const float*)d_in[21];
    const float* g4W  = (const float*)d_in[22];
    const float* g4b  = (const float*)d_in[23];
    const float* f1W  = (const float*)d_in[24];
    const float* f1b  = (const float*)d_in[25];
    const float* f2W  = (const float*)d_in[26];
    const float* f2b  = (const float*)d_in[27];
    const float* f3W  = (const float*)d_in[28];
    const float* f3b  = (const float*)d_in[29];
    float* out = (float*)d_out;

    void *pX0, *pX1, *pX2, *pGsum, *pY1, *pY2, *pBrel, *pG1w, *pXpq, *pXps;
    cudaGetSymbolAddress(&pX0,   d_X0);
    cudaGetSymbolAddress(&pX1,   d_X1);
    cudaGetSymbolAddress(&pX2,   d_X2);
    cudaGetSymbolAddress(&pGsum, d_gsum);
    cudaGetSymbolAddress(&pY1,   d_Y1);
    cudaGetSymbolAddress(&pY2,   d_Y2);
    cudaGetSymbolAddress(&pBrel, d_brel);
    cudaGetSymbolAddress(&pG1w,  d_g1w);
    cudaGetSymbolAddress(&pXpq,  d_xpq);
    cudaGetSymbolAddress(&pXps,  d_xps);
    const float* X0 = (const float*)pX0;
    float* X1 = (float*)pX1;
    float* X2 = (float*)pX2;
    float* Gs = (float*)pGsum;
    float* Y1 = (float*)pY1;
    float* Y2 = (float*)pY2;
    const float* Brel = (const float*)pBrel;
    const float* G1w  = (const float*)pG1w;

    static bool attr_set = false;
    if (!attr_set) {
        cudaFuncSetAttribute(lstm_tc_kernel, cudaFuncAttributeMaxDynamicSharedMemorySize,
                             LSTM_SMEM_BYTES);
        attr_set = true;
    }

    // 0) pack Whh (pre-split tf32) + per-relation g1 bias + dense g1W
    pack_kernel<<<18, 256>>>(qWhh, sWhh);
    bias_rel_kernel<<<64, 256>>>(g1W, g1b);

    // 0b) precompute input projections: xproj = emb @ Wih^T + b (native layout)
    gemm_kernel<<<dim3(2, VPAD / 128), 256>>>(emb, qWih, qb, (float*)pXpq,
                                              VSIZE, 128, 32, 32, 32, 0, 0);
    gemm_kernel<<<dim3(2, VPAD / 128), 256>>>(emb, sWih, sb, (float*)pXps,
                                              VSIZE, 128, 32, 32, 32, 0, 0);

    // 1) tensor-core LSTM recurrence (q + 8 sf streams)
    lstm_tc_kernel<<<NS / 64, 128, LSTM_SMEM_BYTES>>>(q, sf);

    // 2) assemble g1 input [32768, 64]
    build_x0_kernel<<<(NSF + 255) / 256, 256>>>();

    // 3) g-MLP on tensor cores (3xTF32)
    gemm_tc_kernel<<<dim3(GDIM / 64, NSF / 128), 256>>>(X0, G1w, Brel, X1, GDIM, 64, 64, 64, 1, 1);
    gemm_tc_kernel<<<dim3(GDIM / 64, NSF / 128), 256>>>(X1, g2W, g2b, X2, GDIM, GDIM, GDIM, GDIM, 1, 0);
    gemm_tc_kernel<<<dim3(GDIM / 64, NSF / 128), 256>>>(X2, g3W, g3b, X1, GDIM, GDIM, GDIM, GDIM, 1, 0);
    gemm_tc_kernel<<<dim3(GDIM / 64, NSF / 128), 256>>>(X1, g4W, g4b, X2, GDIM, GDIM, GDIM, GDIM, 1, 0);

    // 4) segment-sum over 8 relations
    reduce8_kernel<<<(BSZ * GDIM) / 256, 256>>>();

    // 5) f-head on tensor cores
    gemm_tc_kernel<<<dim3(GDIM / 64,  BSZ / 128), 256>>>(Gs, f1W, f1b, Y1, GDIM,  GDIM,  GDIM,  GDIM,  1, 0);
    gemm_tc_kernel<<<dim3(F2DIM / 64, BSZ / 128), 256>>>(Y1, f2W, f2b, Y2, F2DIM, GDIM,  GDIM,  GDIM,  1, 0);
    gemm_tc_kernel<<<dim3((ADIM + 63) / 64, BSZ / 128), 256>>>(Y2, f3W, f3b, out, ADIM, F2DIM, F2DIM, F2DIM, 0, 0);
}